// round 1
// baseline (speedup 1.0000x reference)
#include <cuda_runtime.h>

#define NB_   4
#define BATCH 8
#define LEN   4096
#define FREQ  80
#define DIM   512
#define HID   2048
#define USEQ  1024
#define C1    128
#define C2    256
#define C3    512
#define H1    2048
#define W1    40
#define H2    1024
#define W2    20
#define MCONV (BATCH*H2*W2)      /* 163840 */
#define K2C   (9*C1)             /* 1152 */
#define K3C   (9*C2)             /* 2304 */
#define KE    (C3*W2)            /* 10240 */
#define MT    (BATCH*USEQ)       /* 8192 */
#define HTOK  (MT*DIM)           /* 4194304 */

// ---------------- scratch (device globals; no allocations) ----------------
__device__ float g_conv1[BATCH*H1*W1*C1];   // (b,h,w,c) channel-last
__device__ float g_col2[MCONV*K2C];
__device__ float g_c2[MCONV*C2];            // (b,h,w,c)
__device__ float g_col3[MCONV*K3C];
__device__ float g_c3[MCONV*C3];            // (b,u,w,c)
__device__ float g_yr[MT*KE];
__device__ float g_t0[HTOK];
__device__ float g_h[HTOK];
__device__ float g_xn[HTOK];
__device__ float g_xk[HTOK];
__device__ float g_xv[HTOK];
__device__ float g_xr[HTOK];
__device__ float g_k[HTOK];
__device__ float g_v[HTOK];
__device__ float g_r[HTOK];
__device__ float g_rwkv[HTOK];
__device__ float g_kk[MT*HID];
__device__ float g_w2r[K2C*C2];
__device__ float g_w3r[K3C*C3];

// ---------------- conv1: direct, (B,1,4096,80) -> (B,2048,40,128) ----------
__global__ void conv1_k(const float* __restrict__ x, const float* __restrict__ w,
                        const float* __restrict__ bias){
  int t = blockIdx.x*256 + threadIdx.x;
  int co = t & 127;
  int rest = t >> 7;
  int wo = rest % W1; rest /= W1;
  int ho = rest % H1; int b = rest / H1;
  float acc = bias[co];
  int hi0 = 2*ho - 1, wi0 = 2*wo - 1;
  #pragma unroll
  for(int kh=0; kh<3; kh++){
    int hi = hi0 + kh;
    if(hi < 0 || hi >= LEN) continue;
    #pragma unroll
    for(int kw=0; kw<3; kw++){
      int wi = wi0 + kw;
      if(wi < 0 || wi >= FREQ) continue;
      acc = fmaf(x[(hi + (long)b*LEN)*FREQ + wi], w[co*9 + kh*3 + kw], acc);
    }
  }
  g_conv1[t] = fmaxf(acc, 0.f);
}

// ---------------- weight reorders: OIHW -> [(kh*3+kw)*CI+ci][co] ------------
__global__ void reorder_w2(const float* __restrict__ w){
  int t = blockIdx.x*256 + threadIdx.x;
  if(t >= C2*C1*9) return;
  int co = t / (C1*9); int rem = t % (C1*9);
  int ci = rem / 9;    int r  = rem % 9;
  g_w2r[(r*C1 + ci)*C2 + co] = w[t];
}
__global__ void reorder_w3(const float* __restrict__ w){
  int t = blockIdx.x*256 + threadIdx.x;
  if(t >= C3*C2*9) return;
  int co = t / (C2*9); int rem = t % (C2*9);
  int ci = rem / 9;    int r  = rem % 9;
  g_w3r[(r*C2 + ci)*C3 + co] = w[t];
}

// ---------------- im2col ----------------------------------------------------
__global__ void im2col2_k(){
  int t = blockIdx.x*256 + threadIdx.x;          // m*K2C + k
  int k = t % K2C; int m = t / K2C;
  int r = k >> 7; int ci = k & 127;
  int kh = r / 3, kw = r % 3;
  int wo = m % W2; int rest = m / W2;
  int ho = rest % H2; int b = rest / H2;
  int hi = 2*ho + kh - 1, wi = 2*wo + kw - 1;
  float v = 0.f;
  if(hi >= 0 && hi < H1 && wi >= 0 && wi < W1)
    v = g_conv1[((b*H1 + hi)*W1 + wi)*C1 + ci];
  g_col2[t] = v;
}
__global__ void im2col3_k(){
  int t = blockIdx.x*256 + threadIdx.x;
  int k = t % K3C; int m = t / K3C;
  int r = k >> 8; int ci = k & 255;
  int kh = r / 3, kw = r % 3;
  int wo = m % W2; int rest = m / W2;
  int ho = rest % H2; int b = rest / H2;
  int hi = ho + kh - 1, wi = wo + kw - 1;
  float v = 0.f;
  if(hi >= 0 && hi < H2 && wi >= 0 && wi < W2)
    v = g_c2[((b*H2 + hi)*W2 + wi)*C2 + ci];
  g_col3[t] = v;
}

// ---------------- generic fp32 SGEMM, 128x128x8, 8x8 microtile --------------
// C[M,N] = epi(act(A[M,K] @ W[K,N] + bias))
// ACT: 0 none, 1 relu, 2 sigmoid, 3 relu^2
// EPI: 0 store, 1 C += acc (residual), 2 C += mul*acc
template<int ACT, int EPI>
__global__ void sgemm_k(int M, int N, int K,
                        const float* __restrict__ A, const float* __restrict__ W,
                        const float* __restrict__ bias, float* __restrict__ C,
                        const float* __restrict__ mul){
  __shared__ float As[8][128];
  __shared__ float Bs[8][128];
  int bm = blockIdx.y, bn = blockIdx.x;
  int tid = threadIdx.x;
  int tr = tid >> 4, tc = tid & 15;
  const float* Ab = A + (long)bm*128*K;
  const float* Wb = W + bn*128;
  float acc[8][8];
  #pragma unroll
  for(int i=0;i<8;i++)
    #pragma unroll
    for(int j=0;j<8;j++) acc[i][j] = 0.f;

  int aRow = tid >> 1, aCol = (tid & 1)*4;
  int bRow = tid >> 5, bCol = (tid & 31)*4;

  for(int k0=0; k0<K; k0+=8){
    float4 av = *(const float4*)(Ab + (long)aRow*K + k0 + aCol);
    float4 bv = *(const float4*)(Wb + (long)(k0 + bRow)*N + bCol);
    __syncthreads();
    As[aCol+0][aRow] = av.x; As[aCol+1][aRow] = av.y;
    As[aCol+2][aRow] = av.z; As[aCol+3][aRow] = av.w;
    *(float4*)&Bs[bRow][bCol] = bv;
    __syncthreads();
    #pragma unroll
    for(int kk=0; kk<8; kk++){
      float ar[8], br[8];
      *(float4*)(ar)   = *(const float4*)&As[kk][tr*8];
      *(float4*)(ar+4) = *(const float4*)&As[kk][tr*8+4];
      *(float4*)(br)   = *(const float4*)&Bs[kk][tc*8];
      *(float4*)(br+4) = *(const float4*)&Bs[kk][tc*8+4];
      #pragma unroll
      for(int i=0;i<8;i++)
        #pragma unroll
        for(int j=0;j<8;j++)
          acc[i][j] = fmaf(ar[i], br[j], acc[i][j]);
    }
  }

  int col0 = bn*128 + tc*8;
  #pragma unroll
  for(int i=0;i<8;i++){
    long row = (long)bm*128 + tr*8 + i;
    float* cp = C + row*N + col0;
    float r8[8];
    #pragma unroll
    for(int j=0;j<8;j++){
      float vv = acc[i][j];
      if(bias) vv += bias[col0 + j];
      if(ACT == 1)      vv = fmaxf(vv, 0.f);
      else if(ACT == 2) vv = 1.f/(1.f + __expf(-vv));
      else if(ACT == 3){ vv = fmaxf(vv, 0.f); vv = vv*vv; }
      r8[j] = vv;
    }
    if(EPI == 1){
      #pragma unroll
      for(int j=0;j<8;j++) r8[j] += cp[j];
    } else if(EPI == 2){
      const float* mp = mul + row*N + col0;
      #pragma unroll
      for(int j=0;j<8;j++) r8[j] = cp[j] + mp[j]*r8[j];
    }
    *(float4*)cp     = make_float4(r8[0], r8[1], r8[2], r8[3]);
    *(float4*)(cp+4) = make_float4(r8[4], r8[5], r8[6], r8[7]);
  }
}

// ---------------- reshape (b,u,w,c) -> (b,u, c*20+w) -------------------------
__global__ void reshape_k(){
  __shared__ float sm[KE];
  int m = blockIdx.x;
  const float* src = g_c3 + (long)m*KE;   // contiguous: idx = w*512 + c
  for(int i=threadIdx.x; i<KE; i+=256){
    int w = i / 512, c = i & 511;
    sm[c*W2 + w] = src[i];
  }
  __syncthreads();
  float* dst = g_yr + (long)m*KE;
  for(int i=threadIdx.x; i<KE; i+=256) dst[i] = sm[i];
}

// ---------------- LayerNorm over D=512, one block (128 thr) per token --------
__global__ void ln_k(const float* __restrict__ x, const float* __restrict__ gw,
                     const float* __restrict__ gb, float* __restrict__ o){
  int m = blockIdx.x;
  int tid = threadIdx.x;
  const float* xr = x + (long)m*DIM;
  float v[4]; float s = 0.f, sq = 0.f;
  #pragma unroll
  for(int j=0;j<4;j++){ float t = xr[tid + j*128]; v[j] = t; s += t; sq += t*t; }
  #pragma unroll
  for(int off=16; off; off>>=1){
    s  += __shfl_xor_sync(0xffffffffu, s,  off);
    sq += __shfl_xor_sync(0xffffffffu, sq, off);
  }
  __shared__ float ss[4], sqs[4];
  if((tid & 31) == 0){ ss[tid>>5] = s; sqs[tid>>5] = sq; }
  __syncthreads();
  s  = (ss[0]+ss[1]) + (ss[2]+ss[3]);
  sq = (sqs[0]+sqs[1]) + (sqs[2]+sqs[3]);
  float mean = s * (1.f/DIM);
  float var  = sq * (1.f/DIM) - mean*mean;
  float rstd = rsqrtf(var + 1e-5f);
  float* orow = o + (long)m*DIM;
  #pragma unroll
  for(int j=0;j<4;j++){
    int d = tid + j*128;
    orow[d] = (v[j] - mean)*rstd*gw[d] + gb[d];
  }
}

// ---------------- time-shift mixes -------------------------------------------
__global__ void mix3_k(const float* __restrict__ xn, const float* __restrict__ mk,
                       const float* __restrict__ mv, const float* __restrict__ mr){
  int t = blockIdx.x*256 + threadIdx.x;
  int d = t & (DIM-1);
  int tok = (t >> 9) & (USEQ-1);
  float cur = xn[t];
  float sh = tok ? xn[t - DIM] : 0.f;
  float dcs = cur - sh;
  g_xk[t] = fmaf(dcs, mk[d], sh);
  g_xv[t] = fmaf(dcs, mv[d], sh);
  g_xr[t] = fmaf(dcs, mr[d], sh);
}
__global__ void mix2_k(const float* __restrict__ xn, const float* __restrict__ mk,
                       const float* __restrict__ mr){
  int t = blockIdx.x*256 + threadIdx.x;
  int d = t & (DIM-1);
  int tok = (t >> 9) & (USEQ-1);
  float cur = xn[t];
  float sh = tok ? xn[t - DIM] : 0.f;
  float dcs = cur - sh;
  g_xk[t] = fmaf(dcs, mk[d], sh);
  g_xr[t] = fmaf(dcs, mr[d], sh);
}

// ---------------- WKV scan (fused with r gating): out = r * wkv --------------
__global__ void wkv_k(const float* __restrict__ k, const float* __restrict__ v,
                      const float* __restrict__ r,
                      const float* __restrict__ dec, const float* __restrict__ fir,
                      float* __restrict__ out){
  int t = blockIdx.x*blockDim.x + threadIdx.x;   // 4096 threads (b,d)
  int d = t & (DIM-1); int b = t >> 9;
  float w = -__expf(dec[d]);
  float u = fir[d];
  float aa = 0.f, bb = 0.f, pp = -1e38f;
  long base = (long)b*USEQ*DIM + d;
  const float* kp = k + base;
  const float* vp = v + base;
  const float* rp = r + base;
  float* op = out + base;
  for(int tt=0; tt<USEQ; tt++){
    long off = (long)tt*DIM;
    float kt = kp[off], vt = vp[off];
    float ww = u + kt;
    float p  = fmaxf(pp, ww);
    float e1 = __expf(pp - p), e2 = __expf(ww - p);
    float o  = (e1*aa + e2*vt) / (e1*bb + e2);
    op[off]  = rp[off] * o;
    float ww2 = pp + w;
    float p2  = fmaxf(ww2, kt);
    e1 = __expf(ww2 - p2); e2 = __expf(kt - p2);
    aa = e1*aa + e2*vt; bb = e1*bb + e2; pp = p2;
  }
}

// ---------------- olens tail --------------------------------------------------
__global__ void tail_k(const int* __restrict__ x_len, float* __restrict__ out, int out_size){
  int b = threadIdx.x;
  if(b < BATCH && out_size >= HTOK + BATCH){
    int l1 = (x_len[b] - 1)/2 + 1;
    int ol = (l1 - 1)/2 + 1;
    out[HTOK + b] = (float)ol;
  }
}

// ---------------- host side ---------------------------------------------------
template <typename T>
static float* symaddr(const T& s){ void* p = nullptr; cudaGetSymbolAddress(&p, s); return (float*)p; }

template<int ACT, int EPI>
static void gemm(int M, int N, int K, const float* A, const float* W,
                 const float* bias, float* C, const float* mul){
  dim3 grid(N/128, M/128);
  sgemm_k<ACT,EPI><<<grid, 256>>>(M, N, K, A, W, bias, C, mul);
}

extern "C" void kernel_launch(void* const* d_in, const int* in_sizes, int n_in,
                              void* d_out, int out_size){
  const float* x       = (const float*)d_in[0];
  const int*   x_len   = (const int*)  d_in[1];
  const float* conv1_w = (const float*)d_in[2];
  const float* conv1_b = (const float*)d_in[3];
  const float* conv2_w = (const float*)d_in[4];
  const float* conv2_b = (const float*)d_in[5];
  const float* conv3_w = (const float*)d_in[6];
  const float* conv3_b = (const float*)d_in[7];
  const float* embed_w = (const float*)d_in[8];
  const float* embed_b = (const float*)d_in[9];
  const float* eln_g   = (const float*)d_in[10];
  const float* eln_b   = (const float*)d_in[11];
  const float* lag     = (const float*)d_in[12];
  const float* lab     = (const float*)d_in[13];
  const float* dec     = (const float*)d_in[14];
  const float* fir     = (const float*)d_in[15];
  const float* amk     = (const float*)d_in[16];
  const float* amv     = (const float*)d_in[17];
  const float* amr     = (const float*)d_in[18];
  const float* awk     = (const float*)d_in[19];
  const float* awv     = (const float*)d_in[20];
  const float* awr     = (const float*)d_in[21];
  const float* awo     = (const float*)d_in[22];
  const float* lfg     = (const float*)d_in[23];
  const float* lfb     = (const float*)d_in[24];
  const float* fmk     = (const float*)d_in[25];
  const float* fmr     = (const float*)d_in[26];
  const float* fwk     = (const float*)d_in[27];
  const float* fwv     = (const float*)d_in[28];
  const float* fwr     = (const float*)d_in[29];
  const float* flg     = (const float*)d_in[30];
  const float* flb     = (const float*)d_in[31];
  float* out = (float*)d_out;

  float* p_col2 = symaddr(g_col2);
  float* p_c2   = symaddr(g_c2);
  float* p_col3 = symaddr(g_col3);
  float* p_c3   = symaddr(g_c3);
  float* p_yr   = symaddr(g_yr);
  float* p_t0   = symaddr(g_t0);
  float* p_h    = symaddr(g_h);
  float* p_xn   = symaddr(g_xn);
  float* p_xk   = symaddr(g_xk);
  float* p_xv   = symaddr(g_xv);
  float* p_xr   = symaddr(g_xr);
  float* p_k    = symaddr(g_k);
  float* p_v    = symaddr(g_v);
  float* p_r    = symaddr(g_r);
  float* p_rwkv = symaddr(g_rwkv);
  float* p_kk   = symaddr(g_kk);
  float* p_w2r  = symaddr(g_w2r);
  float* p_w3r  = symaddr(g_w3r);

  // conv frontend
  conv1_k<<<(BATCH*H1*W1*C1)/256, 256>>>(x, conv1_w, conv1_b);
  reorder_w2<<<(C2*C1*9 + 255)/256, 256>>>(conv2_w);
  reorder_w3<<<(C3*C2*9 + 255)/256, 256>>>(conv3_w);
  im2col2_k<<<(MCONV*K2C)/256, 256>>>();
  gemm<1,0>(MCONV, C2, K2C, p_col2, p_w2r, conv2_b, p_c2, nullptr);
  im2col3_k<<<(MCONV*K3C)/256, 256>>>();
  gemm<1,0>(MCONV, C3, K3C, p_col3, p_w3r, conv3_b, p_c3, nullptr);
  reshape_k<<<MT, 256>>>();
  gemm<0,0>(MT, DIM, KE, p_yr, embed_w, embed_b, p_t0, nullptr);
  ln_k<<<MT, 128>>>(p_t0, eln_g, eln_b, p_h);

  // RWKV blocks
  for(int i=0; i<NB_; i++){
    long w2 = (long)i*DIM*DIM;
    // time mixing
    ln_k<<<MT, 128>>>(p_h, lag + i*DIM, lab + i*DIM, p_xn);
    mix3_k<<<HTOK/256, 256>>>(p_xn, amk + i*DIM, amv + i*DIM, amr + i*DIM);
    gemm<0,0>(MT, DIM, DIM, p_xk, awk + w2, nullptr, p_k, nullptr);
    gemm<0,0>(MT, DIM, DIM, p_xv, awv + w2, nullptr, p_v, nullptr);
    gemm<2,0>(MT, DIM, DIM, p_xr, awr + w2, nullptr, p_r, nullptr);
    wkv_k<<<(BATCH*DIM)/256, 256>>>(p_k, p_v, p_r, dec + i*DIM, fir + i*DIM, p_rwkv);
    gemm<0,1>(MT, DIM, DIM, p_rwkv, awo + w2, nullptr, p_h, nullptr);
    // channel mixing
    ln_k<<<MT, 128>>>(p_h, lfg + i*DIM, lfb + i*DIM, p_xn);
    mix2_k<<<HTOK/256, 256>>>(p_xn, fmk + i*DIM, fmr + i*DIM);
    gemm<3,0>(MT, HID, DIM, p_xk, fwk + (long)i*DIM*HID, nullptr, p_kk, nullptr);
    gemm<2,0>(MT, DIM, DIM, p_xr, fwr + w2, nullptr, p_r, nullptr);
    gemm<0,2>(MT, DIM, HID, p_kk, fwv + (long)i*HID*DIM, nullptr, p_h, p_r);
  }

  ln_k<<<MT, 128>>>(p_h, flg, flb, out);
  tail_k<<<1, 32>>>(x_len, out, out_size);
}